// round 1
// baseline (speedup 1.0000x reference)
#include <cuda_runtime.h>
#include <cstdint>

// Problem constants
constexpr int B = 128, L = 1024, V = 512, H = 512, C = 20;
constexpr int H3 = 3 * H;          // 1536
constexpr int NROW = L * B;        // 131072

// ---------------------------------------------------------------------------
// Device scratch (static __device__ arrays: allocation-free per harness rules)
// ---------------------------------------------------------------------------
__device__ float g_T[3][V][H];                    // transposed conv weights (3 MB)
__device__ float g_y[(size_t)NROW * H];           // conv output, 256 MB
__device__ float g_gi[(size_t)NROW * H3];         // input-side gate preacts, 805 MB
__device__ float g_h[2][B * H];                   // double-buffered hidden state
__device__ unsigned g_bar_count;
__device__ unsigned g_bar_gen;

// ---------------------------------------------------------------------------
// Helpers
// ---------------------------------------------------------------------------
__device__ __forceinline__ float to_tf32(float x) {
    uint32_t u;
    asm("cvt.rna.tf32.f32 %0, %1;" : "=r"(u) : "f"(x));
    return __uint_as_float(u);
}

__device__ __forceinline__ void mma_tf32(float c[4], const uint32_t a[4], const uint32_t b[2]) {
    asm volatile(
        "mma.sync.aligned.m16n8k8.row.col.f32.tf32.tf32.f32 "
        "{%0,%1,%2,%3}, {%4,%5,%6,%7}, {%8,%9}, {%0,%1,%2,%3};\n"
        : "+f"(c[0]), "+f"(c[1]), "+f"(c[2]), "+f"(c[3])
        : "r"(a[0]), "r"(a[1]), "r"(a[2]), "r"(a[3]), "r"(b[0]), "r"(b[1]));
}

// ---------------------------------------------------------------------------
// Init: zero hidden state + barrier (must run every launch — graph replays)
// ---------------------------------------------------------------------------
__global__ void init_kernel() {
    const int i = blockIdx.x * blockDim.x + threadIdx.x;
    if (i < 2 * B * H) ((float*)g_h)[i] = 0.0f;
    if (i == 0) { g_bar_count = 0u; g_bar_gen = 0u; }
}

// ---------------------------------------------------------------------------
// Transpose conv_w (H,V,3) -> g_T[k][v][h] for coalesced embedding gathers
// ---------------------------------------------------------------------------
__global__ void transpose_kernel(const float* __restrict__ conv_w) {
    const int idx = blockIdx.x * blockDim.x + threadIdx.x;
    if (idx < H * V * 3) {
        const int k = idx % 3;
        const int v = (idx / 3) % V;
        const int h = idx / (3 * V);
        g_T[k][v][h] = conv_w[idx];
    }
}

// ---------------------------------------------------------------------------
// Embedding "conv": y[t*B+b, :] = relu(T0[x[t-1]] + T1[x[t]] + T2[x[t+1]] + b)
// ---------------------------------------------------------------------------
__global__ void embed_kernel(const int* __restrict__ x, const float* __restrict__ conv_b) {
    const int n = blockIdx.x;      // 0..NROW-1, n = t*B + b
    const int t = n >> 7;
    const int b = n & 127;
    const int x0 = x[b * L + t];
    const int xm = (t > 0) ? x[b * L + t - 1] : -1;
    const int xp = (t < L - 1) ? x[b * L + t + 1] : -1;
    const int hb = threadIdx.x * 4;

    float4 acc = *(const float4*)(conv_b + hb);
    {
        const float4 e = *(const float4*)(&g_T[1][x0][hb]);
        acc.x += e.x; acc.y += e.y; acc.z += e.z; acc.w += e.w;
    }
    if (xm >= 0) {
        const float4 e = *(const float4*)(&g_T[0][xm][hb]);
        acc.x += e.x; acc.y += e.y; acc.z += e.z; acc.w += e.w;
    }
    if (xp >= 0) {
        const float4 e = *(const float4*)(&g_T[2][xp][hb]);
        acc.x += e.x; acc.y += e.y; acc.z += e.z; acc.w += e.w;
    }
    acc.x = fmaxf(acc.x, 0.0f);
    acc.y = fmaxf(acc.y, 0.0f);
    acc.z = fmaxf(acc.z, 0.0f);
    acc.w = fmaxf(acc.w, 0.0f);
    *(float4*)(g_y + (size_t)n * H + hb) = acc;
}

// ---------------------------------------------------------------------------
// gi = y @ w_ih^T + b_ih   (tf32 mma.sync NT GEMM, M=131072 N=1536 K=512)
// CTA tile 128x64, 8 warps (4x2), warp tile 32x32 = (2 m16) x (4 n8)
// ---------------------------------------------------------------------------
__global__ void __launch_bounds__(256) gi_gemm_kernel(const float* __restrict__ w_ih,
                                                      const float* __restrict__ b_ih) {
    __shared__ float As[128][36];
    __shared__ float Bs[64][36];
    const int tid = threadIdx.x;
    const int warp = tid >> 5, lane = tid & 31;
    const int g = lane >> 2, tig = lane & 3;
    const int wm = (warp >> 1) * 32;
    const int wn = (warp & 1) * 32;
    const size_t row0 = (size_t)blockIdx.y * 128;
    const int col0 = blockIdx.x * 64;

    float c[2][4][4];
#pragma unroll
    for (int mi = 0; mi < 2; mi++)
#pragma unroll
        for (int ni = 0; ni < 4; ni++)
#pragma unroll
            for (int q = 0; q < 4; q++) c[mi][ni][q] = 0.0f;

    const int ar = tid >> 3;
    const int ac = (tid & 7) * 4;
    const float* Ap = g_y + (row0 + ar) * H + ac;
    const float* Bp = w_ih + (size_t)(col0 + ar) * H + ac;

    float4 apf[4], bpf[2];
#pragma unroll
    for (int i = 0; i < 4; i++) apf[i] = *(const float4*)(Ap + (size_t)(32 * i) * H);
#pragma unroll
    for (int i = 0; i < 2; i++) bpf[i] = *(const float4*)(Bp + (size_t)(32 * i) * H);

    for (int kt = 0; kt < 16; kt++) {
#pragma unroll
        for (int i = 0; i < 4; i++) {
            float* d = &As[ar + 32 * i][ac];
            d[0] = to_tf32(apf[i].x); d[1] = to_tf32(apf[i].y);
            d[2] = to_tf32(apf[i].z); d[3] = to_tf32(apf[i].w);
        }
#pragma unroll
        for (int i = 0; i < 2; i++) {
            float* d = &Bs[ar + 32 * i][ac];
            d[0] = to_tf32(bpf[i].x); d[1] = to_tf32(bpf[i].y);
            d[2] = to_tf32(bpf[i].z); d[3] = to_tf32(bpf[i].w);
        }
        __syncthreads();
        if (kt < 15) {
            const float* Ap2 = Ap + (kt + 1) * 32;
            const float* Bp2 = Bp + (kt + 1) * 32;
#pragma unroll
            for (int i = 0; i < 4; i++) apf[i] = *(const float4*)(Ap2 + (size_t)(32 * i) * H);
#pragma unroll
            for (int i = 0; i < 2; i++) bpf[i] = *(const float4*)(Bp2 + (size_t)(32 * i) * H);
        }
#pragma unroll
        for (int k8 = 0; k8 < 4; k8++) {
            const int kk = k8 * 8 + tig;
            uint32_t a[2][4];
#pragma unroll
            for (int mi = 0; mi < 2; mi++) {
                const int r0 = wm + mi * 16;
                a[mi][0] = __float_as_uint(As[r0 + g][kk]);
                a[mi][1] = __float_as_uint(As[r0 + g + 8][kk]);
                a[mi][2] = __float_as_uint(As[r0 + g][kk + 4]);
                a[mi][3] = __float_as_uint(As[r0 + g + 8][kk + 4]);
            }
#pragma unroll
            for (int ni = 0; ni < 4; ni++) {
                uint32_t bb[2];
                const int nr = wn + ni * 8 + g;
                bb[0] = __float_as_uint(Bs[nr][kk]);
                bb[1] = __float_as_uint(Bs[nr][kk + 4]);
#pragma unroll
                for (int mi = 0; mi < 2; mi++) mma_tf32(c[mi][ni], a[mi], bb);
            }
        }
        __syncthreads();
    }
    // epilogue: + bias, store fp32
#pragma unroll
    for (int mi = 0; mi < 2; mi++) {
        const size_t r0 = row0 + wm + mi * 16 + g;
#pragma unroll
        for (int ni = 0; ni < 4; ni++) {
            const int cc = col0 + wn + ni * 8 + 2 * tig;
            const float b0 = b_ih[cc], b1 = b_ih[cc + 1];
            float* C0 = g_gi + r0 * H3 + cc;
            float* C1 = g_gi + (r0 + 8) * H3 + cc;
            C0[0] = c[mi][ni][0] + b0; C0[1] = c[mi][ni][1] + b1;
            C1[0] = c[mi][ni][2] + b0; C1[1] = c[mi][ni][3] + b1;
        }
    }
}

// ---------------------------------------------------------------------------
// Persistent GRU kernel: 64 CTAs, each owns 8 hidden dims (24 gh columns).
// w_hh slice resident in SMEM (tf32), h double-buffered in global, global
// barrier per timestep. Per-CTA tile: gh[128 rows x 24 cols], K=512.
// ---------------------------------------------------------------------------
constexpr int GCTAS = 64;
constexpr int WC_LD = 516;       // 24 rows x 516 stride (bank-conflict free)
constexpr int HS_LD = 36;        // 128 rows x 36 stride
constexpr int GRU_SMEM = (24 * WC_LD + 128 * HS_LD) * 4;   // 67968 B

__global__ void __launch_bounds__(256) gru_kernel(const float* __restrict__ w_hh,
                                                  const float* __restrict__ b_hh) {
    extern __shared__ float sm[];
    float* Wc = sm;                    // [24][WC_LD] tf32 weights (r,z,n strips)
    float* Hs = sm + 24 * WC_LD;       // [128][HS_LD] current h chunk

    const int tid = threadIdx.x;
    const int warp = tid >> 5, lane = tid & 31;
    const int g = lane >> 2, tig = lane & 3;
    const int j0 = blockIdx.x * 8;     // this CTA's hidden strip

    // Load w_hh slice (rows j0..j0+7 of each gate) into SMEM, tf32-rounded
    for (int i = tid; i < 24 * H; i += 256) {
        const int lr = i >> 9, k = i & 511;
        const int grow = (lr >> 3) * H + j0 + (lr & 7);
        Wc[lr * WC_LD + k] = to_tf32(w_hh[(size_t)grow * H + k]);
    }
    const int Jb = j0 + 2 * tig;
    const float bhr0 = b_hh[Jb],         bhr1 = b_hh[Jb + 1];
    const float bhz0 = b_hh[H + Jb],     bhz1 = b_hh[H + Jb + 1];
    const float bhn0 = b_hh[2 * H + Jb], bhn1 = b_hh[2 * H + Jb + 1];
    __syncthreads();

    int p = 0;
    for (int t = 0; t < L; t++) {
        float c[3][4] = {};
        const float* hcur = g_h[p];
        float* hnxt = g_h[p ^ 1];

        for (int kc = 0; kc < 16; kc++) {
            __syncthreads();   // previous mma reads done before overwrite
#pragma unroll
            for (int i = 0; i < 4; i++) {
                const int r = (tid >> 3) + 32 * i;
                const float4 v = *(const float4*)(hcur + r * H + kc * 32 + (tid & 7) * 4);
                float* d = &Hs[r * HS_LD + (tid & 7) * 4];
                d[0] = to_tf32(v.x); d[1] = to_tf32(v.y);
                d[2] = to_tf32(v.z); d[3] = to_tf32(v.w);
            }
            __syncthreads();
#pragma unroll
            for (int k8 = 0; k8 < 4; k8++) {
                const int kk = k8 * 8 + tig;
                uint32_t a[4];
                const int rb = warp * 16;
                a[0] = __float_as_uint(Hs[(rb + g) * HS_LD + kk]);
                a[1] = __float_as_uint(Hs[(rb + g + 8) * HS_LD + kk]);
                a[2] = __float_as_uint(Hs[(rb + g) * HS_LD + kk + 4]);
                a[3] = __float_as_uint(Hs[(rb + g + 8) * HS_LD + kk + 4]);
#pragma unroll
                for (int nb = 0; nb < 3; nb++) {
                    uint32_t bb[2];
                    const float* wrow = &Wc[(nb * 8 + g) * WC_LD + kc * 32];
                    bb[0] = __float_as_uint(wrow[kk]);
                    bb[1] = __float_as_uint(wrow[kk + 4]);
                    mma_tf32(c[nb], a, bb);
                }
            }
        }

        // Gate nonlinearity + state update. Thread owns rows {warp*16+g, +8},
        // hidden dims {Jb, Jb+1}; c-frag index = ro*2 + jj.
        const float* gi_t = g_gi + (size_t)t * (B * H3);
#pragma unroll
        for (int ro = 0; ro < 2; ro++) {
            const int R = warp * 16 + g + ro * 8;
            const float* gir = gi_t + (size_t)R * H3;
#pragma unroll
            for (int jj = 0; jj < 2; jj++) {
                const int J = Jb + jj;
                const float ghr = c[0][ro * 2 + jj] + (jj ? bhr1 : bhr0);
                const float ghz = c[1][ro * 2 + jj] + (jj ? bhz1 : bhz0);
                const float ghn = c[2][ro * 2 + jj] + (jj ? bhn1 : bhn0);
                const float r = 1.0f / (1.0f + __expf(-(gir[J] + ghr)));
                const float z = 1.0f / (1.0f + __expf(-(gir[H + J] + ghz)));
                const float n = tanhf(gir[2 * H + J] + r * ghn);
                const float hold = hcur[R * H + J];
                hnxt[R * H + J] = (1.0f - z) * n + z * hold;
            }
        }

        // Grid barrier (64 co-resident CTAs; thread 0 arrives, rest wait at bar)
        __syncthreads();
        if (tid == 0) {
            __threadfence();
            const unsigned target = (unsigned)(t + 1);
            if (atomicAdd(&g_bar_count, 1u) == GCTAS - 1) {
                g_bar_count = 0u;
                __threadfence();
                atomicExch(&g_bar_gen, target);
            } else {
                while (*(volatile unsigned*)&g_bar_gen < target) __nanosleep(64);
                __threadfence();
            }
        }
        __syncthreads();
        p ^= 1;
    }
}

// ---------------------------------------------------------------------------
// Classifier: out[b,c] = h_final[b,:] . cls_w[c,:] + cls_b[c]
// L is even -> final hidden state lives in g_h[0].
// ---------------------------------------------------------------------------
__global__ void classifier_kernel(const float* __restrict__ cls_w,
                                  const float* __restrict__ cls_b,
                                  float* __restrict__ out) {
    const int b = blockIdx.x / C;
    const int cc = blockIdx.x % C;
    const float* h = g_h[0] + b * H;
    const float* w = cls_w + cc * H;
    float s = 0.0f;
    for (int k = threadIdx.x; k < H; k += 64) s += h[k] * w[k];
#pragma unroll
    for (int o = 16; o > 0; o >>= 1) s += __shfl_down_sync(0xffffffffu, s, o);
    __shared__ float red[2];
    if ((threadIdx.x & 31) == 0) red[threadIdx.x >> 5] = s;
    __syncthreads();
    if (threadIdx.x == 0) out[b * C + cc] = red[0] + red[1] + cls_b[cc];
}

// ---------------------------------------------------------------------------
// Launch
// ---------------------------------------------------------------------------
extern "C" void kernel_launch(void* const* d_in, const int* in_sizes, int n_in,
                              void* d_out, int out_size) {
    const int*   x      = (const int*)d_in[0];
    const float* conv_w = (const float*)d_in[1];
    const float* conv_b = (const float*)d_in[2];
    const float* w_ih   = (const float*)d_in[3];
    const float* w_hh   = (const float*)d_in[4];
    const float* b_ih   = (const float*)d_in[5];
    const float* b_hh   = (const float*)d_in[6];
    const float* cls_w  = (const float*)d_in[7];
    const float* cls_b  = (const float*)d_in[8];
    float* out = (float*)d_out;

    cudaFuncSetAttribute(gru_kernel, cudaFuncAttributeMaxDynamicSharedMemorySize, GRU_SMEM);

    init_kernel<<<512, 256>>>();
    transpose_kernel<<<(H * V * 3 + 255) / 256, 256>>>(conv_w);
    embed_kernel<<<NROW, 128>>>(x, conv_b);
    gi_gemm_kernel<<<dim3(H3 / 64, NROW / 128), 256>>>(w_ih, b_ih);
    gru_kernel<<<GCTAS, 256, GRU_SMEM>>>(w_hh, b_hh);
    classifier_kernel<<<B * C, 64>>>(cls_w, cls_b, out);
}

// round 2
// speedup vs baseline: 3.4540x; 3.4540x over previous
#include <cuda_runtime.h>
#include <cstdint>

// Problem constants
constexpr int B = 128, L = 1024, V = 512, H = 512, C = 20;
constexpr int H3 = 3 * H;          // 1536
constexpr int NROW = L * B;        // 131072

// ---------------------------------------------------------------------------
// Device scratch
// ---------------------------------------------------------------------------
__device__ float g_T[3][V][H];                    // transposed conv weights
__device__ float g_y[(size_t)NROW * H];           // conv output
__device__ float g_gi[(size_t)NROW * H3];         // input-side gate preacts
__device__ float g_h[2][B * H];                   // double-buffered hidden state
__device__ unsigned g_bar_count;
__device__ unsigned g_bar_gen;

// ---------------------------------------------------------------------------
// Helpers
// ---------------------------------------------------------------------------
__device__ __forceinline__ float to_tf32(float x) {
    uint32_t u;
    asm("cvt.rna.tf32.f32 %0, %1;" : "=r"(u) : "f"(x));
    return __uint_as_float(u);
}

__device__ __forceinline__ void mma_tf32(float c[4], const uint32_t a[4], const uint32_t b[2]) {
    asm volatile(
        "mma.sync.aligned.m16n8k8.row.col.f32.tf32.tf32.f32 "
        "{%0,%1,%2,%3}, {%4,%5,%6,%7}, {%8,%9}, {%0,%1,%2,%3};\n"
        : "+f"(c[0]), "+f"(c[1]), "+f"(c[2]), "+f"(c[3])
        : "r"(a[0]), "r"(a[1]), "r"(a[2]), "r"(a[3]), "r"(b[0]), "r"(b[1]));
}

__device__ __forceinline__ void cp16(float* dst_smem, const float* src) {
    uint32_t d = (uint32_t)__cvta_generic_to_shared(dst_smem);
    asm volatile("cp.async.cg.shared.global [%0], [%1], 16;" :: "r"(d), "l"(src));
}

// ---------------------------------------------------------------------------
// Init (runs every launch — graph replays)
// ---------------------------------------------------------------------------
__global__ void init_kernel() {
    const int i = blockIdx.x * blockDim.x + threadIdx.x;
    if (i < 2 * B * H) ((float*)g_h)[i] = 0.0f;
    if (i == 0) { g_bar_count = 0u; g_bar_gen = 0u; }
}

// ---------------------------------------------------------------------------
// Transpose conv_w (H,V,3) -> g_T[k][v][h]
// ---------------------------------------------------------------------------
__global__ void transpose_kernel(const float* __restrict__ conv_w) {
    const int idx = blockIdx.x * blockDim.x + threadIdx.x;
    if (idx < H * V * 3) {
        const int k = idx % 3;
        const int v = (idx / 3) % V;
        const int h = idx / (3 * V);
        g_T[k][v][h] = conv_w[idx];
    }
}

// ---------------------------------------------------------------------------
// Embedding "conv"
// ---------------------------------------------------------------------------
__global__ void embed_kernel(const int* __restrict__ x, const float* __restrict__ conv_b) {
    const int n = blockIdx.x;      // n = t*B + b
    const int t = n >> 7;
    const int b = n & 127;
    const int x0 = x[b * L + t];
    const int xm = (t > 0) ? x[b * L + t - 1] : -1;
    const int xp = (t < L - 1) ? x[b * L + t + 1] : -1;
    const int hb = threadIdx.x * 4;

    float4 acc = *(const float4*)(conv_b + hb);
    {
        const float4 e = *(const float4*)(&g_T[1][x0][hb]);
        acc.x += e.x; acc.y += e.y; acc.z += e.z; acc.w += e.w;
    }
    if (xm >= 0) {
        const float4 e = *(const float4*)(&g_T[0][xm][hb]);
        acc.x += e.x; acc.y += e.y; acc.z += e.z; acc.w += e.w;
    }
    if (xp >= 0) {
        const float4 e = *(const float4*)(&g_T[2][xp][hb]);
        acc.x += e.x; acc.y += e.y; acc.z += e.z; acc.w += e.w;
    }
    acc.x = fmaxf(acc.x, 0.0f);
    acc.y = fmaxf(acc.y, 0.0f);
    acc.z = fmaxf(acc.z, 0.0f);
    acc.w = fmaxf(acc.w, 0.0f);
    *(float4*)(g_y + (size_t)n * H + hb) = acc;
}

// ---------------------------------------------------------------------------
// gi = y @ w_ih^T + b_ih  (unchanged from R1 — known working)
// ---------------------------------------------------------------------------
__global__ void __launch_bounds__(256) gi_gemm_kernel(const float* __restrict__ w_ih,
                                                      const float* __restrict__ b_ih) {
    __shared__ float As[128][36];
    __shared__ float Bs[64][36];
    const int tid = threadIdx.x;
    const int warp = tid >> 5, lane = tid & 31;
    const int g = lane >> 2, tig = lane & 3;
    const int wm = (warp >> 1) * 32;
    const int wn = (warp & 1) * 32;
    const size_t row0 = (size_t)blockIdx.y * 128;
    const int col0 = blockIdx.x * 64;

    float c[2][4][4];
#pragma unroll
    for (int mi = 0; mi < 2; mi++)
#pragma unroll
        for (int ni = 0; ni < 4; ni++)
#pragma unroll
            for (int q = 0; q < 4; q++) c[mi][ni][q] = 0.0f;

    const int ar = tid >> 3;
    const int ac = (tid & 7) * 4;
    const float* Ap = g_y + (row0 + ar) * H + ac;
    const float* Bp = w_ih + (size_t)(col0 + ar) * H + ac;

    float4 apf[4], bpf[2];
#pragma unroll
    for (int i = 0; i < 4; i++) apf[i] = *(const float4*)(Ap + (size_t)(32 * i) * H);
#pragma unroll
    for (int i = 0; i < 2; i++) bpf[i] = *(const float4*)(Bp + (size_t)(32 * i) * H);

    for (int kt = 0; kt < 16; kt++) {
#pragma unroll
        for (int i = 0; i < 4; i++) {
            float* d = &As[ar + 32 * i][ac];
            d[0] = to_tf32(apf[i].x); d[1] = to_tf32(apf[i].y);
            d[2] = to_tf32(apf[i].z); d[3] = to_tf32(apf[i].w);
        }
#pragma unroll
        for (int i = 0; i < 2; i++) {
            float* d = &Bs[ar + 32 * i][ac];
            d[0] = to_tf32(bpf[i].x); d[1] = to_tf32(bpf[i].y);
            d[2] = to_tf32(bpf[i].z); d[3] = to_tf32(bpf[i].w);
        }
        __syncthreads();
        if (kt < 15) {
            const float* Ap2 = Ap + (kt + 1) * 32;
            const float* Bp2 = Bp + (kt + 1) * 32;
#pragma unroll
            for (int i = 0; i < 4; i++) apf[i] = *(const float4*)(Ap2 + (size_t)(32 * i) * H);
#pragma unroll
            for (int i = 0; i < 2; i++) bpf[i] = *(const float4*)(Bp2 + (size_t)(32 * i) * H);
        }
#pragma unroll
        for (int k8 = 0; k8 < 4; k8++) {
            const int kk = k8 * 8 + tig;
            uint32_t a[2][4];
#pragma unroll
            for (int mi = 0; mi < 2; mi++) {
                const int r0 = wm + mi * 16;
                a[mi][0] = __float_as_uint(As[r0 + g][kk]);
                a[mi][1] = __float_as_uint(As[r0 + g + 8][kk]);
                a[mi][2] = __float_as_uint(As[r0 + g][kk + 4]);
                a[mi][3] = __float_as_uint(As[r0 + g + 8][kk + 4]);
            }
#pragma unroll
            for (int ni = 0; ni < 4; ni++) {
                uint32_t bb[2];
                const int nr = wn + ni * 8 + g;
                bb[0] = __float_as_uint(Bs[nr][kk]);
                bb[1] = __float_as_uint(Bs[nr][kk + 4]);
#pragma unroll
                for (int mi = 0; mi < 2; mi++) mma_tf32(c[mi][ni], a[mi], bb);
            }
        }
        __syncthreads();
    }
#pragma unroll
    for (int mi = 0; mi < 2; mi++) {
        const size_t r0 = row0 + wm + mi * 16 + g;
#pragma unroll
        for (int ni = 0; ni < 4; ni++) {
            const int cc = col0 + wn + ni * 8 + 2 * tig;
            const float b0 = b_ih[cc], b1 = b_ih[cc + 1];
            float* C0 = g_gi + r0 * H3 + cc;
            float* C1 = g_gi + (r0 + 8) * H3 + cc;
            C0[0] = c[mi][ni][0] + b0; C0[1] = c[mi][ni][1] + b1;
            C1[0] = c[mi][ni][2] + b0; C1[1] = c[mi][ni][3] + b1;
        }
    }
}

// ---------------------------------------------------------------------------
// Persistent GRU kernel v2: 64 CTAs x 128 threads (4 warps, m32 x n24 each).
// w_hh slice resident in SMEM; h broadcast via cp.async 4-stage ring (L2-
// coherent); spin barrier (no nanosleep); gi/h_old prefetched per step.
// ---------------------------------------------------------------------------
constexpr int GCTAS = 64;
constexpr int WC_LD = 516;       // weights stride (floats)
constexpr int HS_LD = 36;        // h-tile stride (floats)
constexpr int NSTG = 4;          // cp.async ring depth
constexpr int GRU_SMEM = (24 * WC_LD + NSTG * 128 * HS_LD) * 4;   // 123264 B

__device__ __forceinline__ void issue_cp(const float* hcur, int kc, int buf,
                                         float* Hs, int r8, int t8) {
    float* dst = Hs + buf * (128 * HS_LD) + t8 * 4;
    const float* src = hcur + kc * 32 + t8 * 4;
#pragma unroll
    for (int pp = 0; pp < 8; pp++) {
        const int r = r8 + 16 * pp;
        cp16(dst + r * HS_LD, src + r * H);
    }
    asm volatile("cp.async.commit_group;" ::: "memory");
}

__global__ void __launch_bounds__(128, 1) gru_kernel(const float* __restrict__ w_hh,
                                                     const float* __restrict__ b_hh) {
    extern __shared__ float sm[];
    float* Wc = sm;                       // [24][WC_LD] weights (r,z,n strips)
    float* Hs = sm + 24 * WC_LD;          // [NSTG][128][HS_LD]

    const int tid = threadIdx.x;
    const int warp = tid >> 5, lane = tid & 31;
    const int g = lane >> 2, tig = lane & 3;
    const int rb = warp * 32;
    const int j0 = blockIdx.x * 8;
    const int r8 = tid >> 3, t8 = tid & 7;

    // Load w_hh slice (raw fp32; HMMA truncates to tf32 itself)
    for (int i = tid; i < 24 * H; i += 128) {
        const int lr = i >> 9, k = i & 511;
        Wc[lr * WC_LD + k] = w_hh[(size_t)((lr >> 3) * H + j0 + (lr & 7)) * H + k];
    }
    const int Jb = j0 + 2 * tig;
    float2 bh[3];
    bh[0] = *(const float2*)(b_hh + Jb);
    bh[1] = *(const float2*)(b_hh + H + Jb);
    bh[2] = *(const float2*)(b_hh + 2 * H + Jb);
    __syncthreads();

    int p = 0;
    for (int t = 0; t < L; t++) {
        const float* hcur = g_h[p];
        float* hnxt = g_h[p ^ 1];

        // Prefetch this step's gi and h_old (own columns — written by this SM)
        const float* gi_t = g_gi + (size_t)t * (B * H3);
        float2 gv[4][3], hold[4];
#pragma unroll
        for (int ro = 0; ro < 4; ro++) {
            const int R = rb + (ro >> 1) * 16 + (ro & 1) * 8 + g;
            const float* gr = gi_t + (size_t)R * H3;
            gv[ro][0] = *(const float2*)(gr + Jb);
            gv[ro][1] = *(const float2*)(gr + H + Jb);
            gv[ro][2] = *(const float2*)(gr + 2 * H + Jb);
            hold[ro] = *(const float2*)(hcur + R * H + Jb);
        }

        // cp.async ring prologue: stages 0..2
#pragma unroll
        for (int s = 0; s < 3; s++) issue_cp(hcur, s, s, Hs, r8, t8);

        float c[2][3][4] = {};
#pragma unroll 4
        for (int kc = 0; kc < 16; kc++) {
            asm volatile("cp.async.wait_group 2;" ::: "memory");
            __syncthreads();
            const float* Hb = Hs + (kc & 3) * (128 * HS_LD);
#pragma unroll
            for (int k8 = 0; k8 < 4; k8++) {
                const int kk = k8 * 8 + tig;
                uint32_t a[2][4];
#pragma unroll
                for (int mi = 0; mi < 2; mi++) {
                    const float* hb = Hb + (rb + mi * 16 + g) * HS_LD;
                    a[mi][0] = __float_as_uint(hb[kk]);
                    a[mi][1] = __float_as_uint(hb[8 * HS_LD + kk]);
                    a[mi][2] = __float_as_uint(hb[kk + 4]);
                    a[mi][3] = __float_as_uint(hb[8 * HS_LD + kk + 4]);
                }
#pragma unroll
                for (int nb = 0; nb < 3; nb++) {
                    const float* wr = Wc + (nb * 8 + g) * WC_LD + kc * 32;
                    uint32_t bb[2];
                    bb[0] = __float_as_uint(wr[kk]);
                    bb[1] = __float_as_uint(wr[kk + 4]);
                    mma_tf32(c[0][nb], a[0], bb);
                    mma_tf32(c[1][nb], a[1], bb);
                }
            }
            if (kc < 13) issue_cp(hcur, kc + 3, (kc + 3) & 3, Hs, r8, t8);
            else asm volatile("cp.async.commit_group;" ::: "memory");
        }

        // Gates + state update. Thread owns rows {rb+g, +8, +16, +24}, cols {Jb, Jb+1}.
#pragma unroll
        for (int ro = 0; ro < 4; ro++) {
            const int R = rb + (ro >> 1) * 16 + (ro & 1) * 8 + g;
            const int mi = ro >> 1, fo = (ro & 1) * 2;
            const float ghr0 = c[mi][0][fo] + bh[0].x, ghr1 = c[mi][0][fo + 1] + bh[0].y;
            const float ghz0 = c[mi][1][fo] + bh[1].x, ghz1 = c[mi][1][fo + 1] + bh[1].y;
            const float ghn0 = c[mi][2][fo] + bh[2].x, ghn1 = c[mi][2][fo + 1] + bh[2].y;
            const float r0 = 1.0f / (1.0f + __expf(-(gv[ro][0].x + ghr0)));
            const float r1 = 1.0f / (1.0f + __expf(-(gv[ro][0].y + ghr1)));
            const float z0 = 1.0f / (1.0f + __expf(-(gv[ro][1].x + ghz0)));
            const float z1 = 1.0f / (1.0f + __expf(-(gv[ro][1].y + ghz1)));
            const float n0 = tanhf(gv[ro][2].x + r0 * ghn0);
            const float n1 = tanhf(gv[ro][2].y + r1 * ghn1);
            float2 hn;
            hn.x = (1.0f - z0) * n0 + z0 * hold[ro].x;
            hn.y = (1.0f - z1) * n1 + z1 * hold[ro].y;
            *(float2*)(hnxt + R * H + Jb) = hn;
        }

        // Grid barrier: tight spin, no nanosleep
        __threadfence();
        __syncthreads();
        if (tid == 0) {
            const unsigned target = (unsigned)(t + 1);
            if (atomicAdd(&g_bar_count, 1u) == GCTAS - 1) {
                atomicExch(&g_bar_count, 0u);
                __threadfence();
                atomicExch(&g_bar_gen, target);
            } else {
                while (*(volatile unsigned*)&g_bar_gen < target) {}
            }
        }
        __syncthreads();
        p ^= 1;
    }
}

// ---------------------------------------------------------------------------
// Classifier
// ---------------------------------------------------------------------------
__global__ void classifier_kernel(const float* __restrict__ cls_w,
                                  const float* __restrict__ cls_b,
                                  float* __restrict__ out) {
    const int b = blockIdx.x / C;
    const int cc = blockIdx.x % C;
    const float* h = g_h[0] + b * H;
    const float* w = cls_w + cc * H;
    float s = 0.0f;
    for (int k = threadIdx.x; k < H; k += 64) s += h[k] * w[k];
#pragma unroll
    for (int o = 16; o > 0; o >>= 1) s += __shfl_down_sync(0xffffffffu, s, o);
    __shared__ float red[2];
    if ((threadIdx.x & 31) == 0) red[threadIdx.x >> 5] = s;
    __syncthreads();
    if (threadIdx.x == 0) out[b * C + cc] = red[0] + red[1] + cls_b[cc];
}

// ---------------------------------------------------------------------------
// Launch
// ---------------------------------------------------------------------------
extern "C" void kernel_launch(void* const* d_in, const int* in_sizes, int n_in,
                              void* d_out, int out_size) {
    const int*   x      = (const int*)d_in[0];
    const float* conv_w = (const float*)d_in[1];
    const float* conv_b = (const float*)d_in[2];
    const float* w_ih   = (const float*)d_in[3];
    const float* w_hh   = (const float*)d_in[4];
    const float* b_ih   = (const float*)d_in[5];
    const float* b_hh   = (const float*)d_in[6];
    const float* cls_w  = (const float*)d_in[7];
    const float* cls_b  = (const float*)d_in[8];
    float* out = (float*)d_out;

    cudaFuncSetAttribute(gru_kernel, cudaFuncAttributeMaxDynamicSharedMemorySize, GRU_SMEM);

    init_kernel<<<512, 256>>>();
    transpose_kernel<<<(H * V * 3 + 255) / 256, 256>>>(conv_w);
    embed_kernel<<<NROW, 128>>>(x, conv_b);
    gi_gemm_kernel<<<dim3(H3 / 64, NROW / 128), 256>>>(w_ih, b_ih);
    gru_kernel<<<GCTAS, 128, GRU_SMEM>>>(w_hh, b_hh);
    classifier_kernel<<<B * C, 64>>>(cls_w, cls_b, out);
}